// round 8
// baseline (speedup 1.0000x reference)
#include <cuda_runtime.h>
#include <math.h>

// Problem constants (B=1)
#define Cc    4      // chunks
#define Hh    8      // heads
#define Ll    1024   // chunk length
#define Dd    64     // head dim
#define Tt    (Cc*Ll)
#define NPAIR 2080   // symmetric (d<=e) pairs: 64*65/2
#define NPAD  2176   // padded to 17*128
#define NVP   68     // padded row: 64 v + Z at col 64 + 3 pad (16B-aligned rows)
#define SCALEF 0.125f
#define EPSF   1e-6f

// ---------------- scratch (device globals; no allocation allowed) -----------
__device__ float g_g   [Cc*Hh*Ll];
__device__ float g_w   [Cc*Hh*Ll];
__device__ float g_qd  [Cc*Hh*Ll];
__device__ float g_gtot[Cc*Hh];
__device__ float g_P   [Cc*Hh*NPAIR*NVP];
__device__ float g_S   [Cc*Hh*NPAIR*NVP];
__device__ float g_intra[Tt*Hh*Dd];
__device__ float g_row  [Tt*Hh];
__device__ unsigned char g_pd[NPAD];
__device__ unsigned char g_pe[NPAD];

// ---------------- K0: pair index tables (padded with clamp) ------------------
__global__ void k_pairs() {
    int i = blockIdx.x * blockDim.x + threadIdx.x;
    if (i >= NPAD) return;
    int ii = (i < NPAIR) ? i : (NPAIR - 1);
    int d = 0, rem = ii;
    while (rem >= (Dd - d)) { rem -= (Dd - d); d++; }
    g_pd[i] = (unsigned char)d;
    g_pe[i] = (unsigned char)(d + rem);
}

// ---------------- K1: gating cumsum + derived weights ------------------------
__global__ void k_gate(const float* __restrict__ logg) {
    int ch = blockIdx.x;           // c*Hh + h
    int c = ch / Hh, h = ch % Hh;
    int l = threadIdx.x;
    __shared__ float sbuf[Ll];
    int t = c * Ll + l;
    sbuf[l] = logg[t * Hh + h];
    __syncthreads();
    for (int off = 1; off < Ll; off <<= 1) {
        float v   = sbuf[l];
        float add = (l >= off) ? sbuf[l - off] : 0.f;
        __syncthreads();
        sbuf[l] = v + add;
        __syncthreads();
    }
    float g    = sbuf[l];
    float gend = sbuf[Ll - 1];
    int idx = ch * Ll + l;
    g_g [idx] = g;
    g_w [idx] = expf(gend - g);
    g_qd[idx] = expf(g);
    if (l == 0) g_gtot[ch] = expf(gend);
}

// ---------------- K2: intra-chunk causal attention ---------------------------
__global__ void __launch_bounds__(128)
k_intra(const float* __restrict__ q, const float* __restrict__ k,
        const float* __restrict__ v) {
    int tl = 7 - blockIdx.x;
    int h = blockIdx.y, c = blockIdx.z;
    int lrow  = tl * 128 + threadIdx.x;
    int tglob = c * Ll + lrow;

    float qreg[Dd];
#pragma unroll
    for (int d = 0; d < Dd; d++)
        qreg[d] = q[(tglob * Hh + h) * Dd + d] * SCALEF;
    float gl = g_g[(c * Hh + h) * Ll + lrow];

    float acc[Dd];
#pragma unroll
    for (int d = 0; d < Dd; d++) acc[d] = 0.f;
    float rowsum = 0.f;

    __shared__ __align__(16) float Ks[64][68];
    __shared__ __align__(16) float Vs[64][68];
    __shared__ float Gs[64];

    int ntile = (tl + 1) * 2;
    for (int st = 0; st < ntile; st++) {
        int sbase = st * 64;
        __syncthreads();
        for (int idx = threadIdx.x; idx < 64 * Dd; idx += 128) {
            int r = idx >> 6, col = idx & 63;
            int ts = c * Ll + sbase + r;
            Ks[r][col] = k[(ts * Hh + h) * Dd + col];
            Vs[r][col] = v[(ts * Hh + h) * Dd + col];
        }
        if (threadIdx.x < 64)
            Gs[threadIdx.x] = g_g[(c * Hh + h) * Ll + sbase + threadIdx.x];
        __syncthreads();

        int smax = lrow - sbase + 1;
        if (smax > 64) smax = 64;
        for (int s = 0; s < smax; s++) {
            const float4* Kr = reinterpret_cast<const float4*>(&Ks[s][0]);
            float s0 = 0.f, s1 = 0.f, s2 = 0.f, s3 = 0.f;
#pragma unroll
            for (int d4 = 0; d4 < 16; d4++) {
                float4 kk = Kr[d4];
                s0 += qreg[4 * d4 + 0] * kk.x;
                s1 += qreg[4 * d4 + 1] * kk.y;
                s2 += qreg[4 * d4 + 2] * kk.z;
                s3 += qreg[4 * d4 + 3] * kk.w;
            }
            float sc = (s0 + s1) + (s2 + s3);
            float a  = __expf(gl - Gs[s]) * sc * sc;
            rowsum += a;
            const float4* Vr = reinterpret_cast<const float4*>(&Vs[s][0]);
#pragma unroll
            for (int d4 = 0; d4 < 16; d4++) {
                float4 vv = Vr[d4];
                acc[4 * d4 + 0] += a * vv.x;
                acc[4 * d4 + 1] += a * vv.y;
                acc[4 * d4 + 2] += a * vv.z;
                acc[4 * d4 + 3] += a * vv.w;
            }
        }
    }
    int ohid = tglob * Hh + h;
#pragma unroll
    for (int d = 0; d < Dd; d++) g_intra[ohid * Dd + d] = acc[d];
    g_row[ohid] = rowsum;
}

// ---------------- K3: per-chunk state build (staged-F register-tiled GEMM) ---
// Block: 128 pairs x 65 v. Threads: 32 pair-groups(4) x 4 v-groups(16).
__global__ void __launch_bounds__(128)
k_state(const float* __restrict__ k, const float* __restrict__ v) {
    int p0 = blockIdx.x * 128;
    int h = blockIdx.y, c = blockIdx.z;
    int ch = c * Hh + h;
    int t = threadIdx.x;

    int d = g_pd[p0 + t];          // this thread's staging pair
    int e = g_pe[p0 + t];
    int pg = t >> 2;               // pair group (4 pairs each)
    int vg = t & 3;                // v group (16 v each)
    int v0 = vg * 16;

    __shared__ __align__(16) float Ks[32][68];
    __shared__ __align__(16) float Vs[32][68];
    __shared__ __align__(16) float Fs[32][132];
    __shared__ float Ws[32];

    float acc[64];
#pragma unroll
    for (int x = 0; x < 64; x++) acc[x] = 0.f;
    float accZ = 0.f;

    for (int lb = 0; lb < Ll; lb += 32) {
        __syncthreads();
        if (t < 32) Ws[t] = g_w[ch * Ll + lb + t];
        for (int idx = t; idx < 32 * Dd; idx += 128) {
            int r = idx >> 6, col = idx & 63;
            int ts = c * Ll + lb + r;
            Ks[r][col] = k[(ts * Hh + h) * Dd + col];
            Vs[r][col] = v[(ts * Hh + h) * Dd + col];
        }
        __syncthreads();
        // stage F: thread t owns pair p0+t for all 32 l; Z accumulates free
#pragma unroll
        for (int j = 0; j < 32; j++) {
            float f = Ws[j] * Ks[j][d] * Ks[j][e];
            Fs[j][t] = f;
            accZ += f;
        }
        __syncthreads();
        // register-tiled GEMM: acc[4 pairs][16 v] += F * V
#pragma unroll 4
        for (int l = 0; l < 32; l++) {
            float4 f4 = *reinterpret_cast<const float4*>(&Fs[l][pg * 4]);
            const float4* Vr = reinterpret_cast<const float4*>(&Vs[l][v0]);
            float4 w0 = Vr[0], w1 = Vr[1], w2 = Vr[2], w3 = Vr[3];
            float fv[4] = {f4.x, f4.y, f4.z, f4.w};
#pragma unroll
            for (int j = 0; j < 4; j++) {
                float f = fv[j];
                acc[j*16+ 0] += f*w0.x; acc[j*16+ 1] += f*w0.y;
                acc[j*16+ 2] += f*w0.z; acc[j*16+ 3] += f*w0.w;
                acc[j*16+ 4] += f*w1.x; acc[j*16+ 5] += f*w1.y;
                acc[j*16+ 6] += f*w1.z; acc[j*16+ 7] += f*w1.w;
                acc[j*16+ 8] += f*w2.x; acc[j*16+ 9] += f*w2.y;
                acc[j*16+10] += f*w2.z; acc[j*16+11] += f*w2.w;
                acc[j*16+12] += f*w3.x; acc[j*16+13] += f*w3.y;
                acc[j*16+14] += f*w3.z; acc[j*16+15] += f*w3.w;
            }
        }
    }
    // store Z (thread t owns pair p0+t)
    if (p0 + t < NPAIR)
        g_P[((size_t)(ch * NPAIR) + p0 + t) * NVP + 64] = accZ;
    // store V-part
#pragma unroll
    for (int j = 0; j < 4; j++) {
        int p = p0 + pg * 4 + j;
        if (p < NPAIR) {
            float* dst = &g_P[((size_t)(ch * NPAIR) + p) * NVP + v0];
#pragma unroll
            for (int x = 0; x < 4; x++)
                *reinterpret_cast<float4*>(&dst[x * 4]) =
                    make_float4(acc[j*16+x*4+0], acc[j*16+x*4+1],
                                acc[j*16+x*4+2], acc[j*16+x*4+3]);
        }
    }
}

// ---------------- K4: prefix scan over chunks --------------------------------
__global__ void k_scan() {
    int idx = blockIdx.x * blockDim.x + threadIdx.x;
    const int per_h = NPAIR * NVP;
    const int tot = Hh * per_h;
    if (idx >= tot) return;
    int h = idx / per_h;
    int rem = idx % per_h;
    int i = rem / NVP;
    float mult = (g_pd[i] == g_pe[i]) ? 1.f : 2.f;
    float s = 0.f;
    for (int c = 0; c < Cc; c++) {
        size_t off = (size_t)(c * Hh + h) * per_h + rem;
        g_S[off] = mult * s;
        s = g_gtot[c * Hh + h] * s + g_P[off];
    }
}

// ---------------- K5: inter-chunk GEMM + combine (staged-Fq register-tiled) --
// Block: 128 rows x 65 v. Threads: 32 row-groups(4) x 4 v-groups(16).
__global__ void __launch_bounds__(128)
k_inter(const float* __restrict__ q, float* __restrict__ out) {
    extern __shared__ float dsm[];
    float* Qs   = dsm;                 // [128][65]
    float* Ss   = Qs + 128 * 65;       // [32][68]
    float* Fq   = Ss + 32 * 68;        // [32][132]
    float* SInv = Fq + 32 * 132;       // [128]
    __shared__ unsigned char Pd2[32], Pe2[32];

    int tl = blockIdx.x, h = blockIdx.y, c = blockIdx.z;
    int ch = c * Hh + h;
    int t = threadIdx.x;
    int rg = t >> 2, vg = t & 3, v0 = vg * 16;

    for (int idx = t; idx < 128 * Dd; idx += 128) {
        int r = idx >> 6, col = idx & 63;
        int tg = c * Ll + tl * 128 + r;
        Qs[r * 65 + col] = q[(tg * Hh + h) * Dd + col] * SCALEF;
    }
    __syncthreads();

    float acc[64];
#pragma unroll
    for (int x = 0; x < 64; x++) acc[x] = 0.f;
    float accZ[4] = {0.f, 0.f, 0.f, 0.f};

    if (c > 0) {
        const float* Sbase = &g_S[(size_t)ch * NPAIR * NVP];
        const float* qrow = &Qs[t * 65];
        for (int ib = 0; ib < NPAIR; ib += 32) {
            __syncthreads();
            // flat float4 copy of S tile (row stride matches: NVP)
            const float4* src = reinterpret_cast<const float4*>(Sbase + (size_t)ib * NVP);
            float4* dstS = reinterpret_cast<float4*>(Ss);
            for (int idx = t; idx < 32 * NVP / 4; idx += 128) dstS[idx] = src[idx];
            if (t < 32) { Pd2[t] = g_pd[ib + t]; Pe2[t] = g_pe[ib + t]; }
            __syncthreads();
            // stage Fq: thread t owns row t for all 32 pairs
#pragma unroll
            for (int ii = 0; ii < 32; ii++)
                Fq[ii * 132 + t] = qrow[Pd2[ii]] * qrow[Pe2[ii]];
            __syncthreads();
            // register-tiled GEMM: acc[4 rows][16 v] += Fq * S
#pragma unroll 4
            for (int ii = 0; ii < 32; ii++) {
                float4 f4 = *reinterpret_cast<const float4*>(&Fq[ii * 132 + rg * 4]);
                const float4* Sr = reinterpret_cast<const float4*>(&Ss[ii * 68 + v0]);
                float4 s0 = Sr[0], s1 = Sr[1], s2 = Sr[2], s3 = Sr[3];
                float fv[4] = {f4.x, f4.y, f4.z, f4.w};
#pragma unroll
                for (int j = 0; j < 4; j++) {
                    float f = fv[j];
                    acc[j*16+ 0] += f*s0.x; acc[j*16+ 1] += f*s0.y;
                    acc[j*16+ 2] += f*s0.z; acc[j*16+ 3] += f*s0.w;
                    acc[j*16+ 4] += f*s1.x; acc[j*16+ 5] += f*s1.y;
                    acc[j*16+ 6] += f*s1.z; acc[j*16+ 7] += f*s1.w;
                    acc[j*16+ 8] += f*s2.x; acc[j*16+ 9] += f*s2.y;
                    acc[j*16+10] += f*s2.z; acc[j*16+11] += f*s2.w;
                    acc[j*16+12] += f*s3.x; acc[j*16+13] += f*s3.y;
                    acc[j*16+14] += f*s3.z; acc[j*16+15] += f*s3.w;
                }
                if (vg == 0) {
                    float sz = Ss[ii * 68 + 64];
                    accZ[0] += f4.x * sz; accZ[1] += f4.y * sz;
                    accZ[2] += f4.z * sz; accZ[3] += f4.w * sz;
                }
            }
        }
    }

    __syncthreads();
    if (vg == 0) {
#pragma unroll
        for (int j = 0; j < 4; j++) {
            int r = rg * 4 + j;
            int tg = c * Ll + tl * 128 + r;
            float qd = g_qd[ch * Ll + tl * 128 + r];
            float den = g_row[tg * Hh + h] + qd * accZ[j];
            SInv[r] = 1.f / fmaxf(den, EPSF);
        }
    }
    __syncthreads();
#pragma unroll
    for (int j = 0; j < 4; j++) {
        int r = rg * 4 + j;
        int tg = c * Ll + tl * 128 + r;
        int ohid = tg * Hh + h;
        float qd = g_qd[ch * Ll + tl * 128 + r];
        float inv = SInv[r];
        const float4* Ir = reinterpret_cast<const float4*>(&g_intra[(size_t)ohid * Dd + v0]);
        float4* Or = reinterpret_cast<float4*>(&out[(size_t)ohid * Dd + v0]);
#pragma unroll
        for (int x = 0; x < 4; x++) {
            float4 iv = Ir[x];
            Or[x] = make_float4((iv.x + qd * acc[j*16+x*4+0]) * inv,
                                (iv.y + qd * acc[j*16+x*4+1]) * inv,
                                (iv.z + qd * acc[j*16+x*4+2]) * inv,
                                (iv.w + qd * acc[j*16+x*4+3]) * inv);
        }
    }
}

// ---------------- host launch -------------------------------------------------
extern "C" void kernel_launch(void* const* d_in, const int* in_sizes, int n_in,
                              void* d_out, int out_size) {
    const float* q  = (const float*)d_in[0];
    const float* k  = (const float*)d_in[1];
    const float* v  = (const float*)d_in[2];
    const float* lg = (const float*)d_in[3];
    float* out = (float*)d_out;

    const int inter_smem = (128 * 65 + 32 * 68 + 32 * 132 + 128) * 4;  // 59392
    cudaFuncSetAttribute(k_inter, cudaFuncAttributeMaxDynamicSharedMemorySize,
                         inter_smem);

    k_pairs<<<(NPAD + 127) / 128, 128>>>();
    k_gate <<<Cc * Hh, Ll>>>(lg);
    k_intra<<<dim3(8, Hh, Cc), 128>>>(q, k, v);
    k_state<<<dim3(NPAD / 128, Hh, Cc), 128>>>(k, v);
    k_scan <<<(Hh * NPAIR * NVP + 255) / 256, 256>>>();
    k_inter<<<dim3(8, Hh, Cc), 128, inter_smem>>>(q, out);
}

// round 9
// speedup vs baseline: 1.0604x; 1.0604x over previous
#include <cuda_runtime.h>
#include <math.h>

// Problem constants (B=1)
#define Cc    4      // chunks
#define Hh    8      // heads
#define Ll    1024   // chunk length
#define Dd    64     // head dim
#define Tt    (Cc*Ll)
#define NQUAD 544    // quads: (d, e0) with e0 = (d&~3)+4j, e0..e0+3
#define NSLOT 2176   // NQUAD*4 slots (invalid e<d slots have multiplier 0)
#define NVP   68     // padded row: 64 v + Z at col 64 + 3 pad
#define SCALEF 0.125f
#define EPSF   1e-6f

// ---------------- scratch (device globals; no allocation allowed) -----------
__device__ float g_g   [Cc*Hh*Ll];
__device__ float g_w   [Cc*Hh*Ll];
__device__ float g_qd  [Cc*Hh*Ll];
__device__ float g_gtot[Cc*Hh];
__device__ float g_P   [Cc*Hh*NSLOT*NVP];
__device__ float g_S   [Cc*Hh*NSLOT*NVP];
__device__ float g_intra[Tt*Hh*Dd];
__device__ float g_row  [Tt*Hh];
__device__ int   g_qd8 [NQUAD];     // quad -> d
__device__ int   g_qe0 [NQUAD];     // quad -> e0
__device__ float g_msl [NSLOT];     // slot multiplier: 0 (e<d), 1 (e==d), 2 (e>d)

// ---------------- K0: quad tables ---------------------------------------------
__global__ void k_pairs() {
    int qq = blockIdx.x * blockDim.x + threadIdx.x;
    if (qq >= NQUAD) return;
    int d = 0, base = 0;
    for (;;) {
        int cnt = 16 - (d >> 2);      // quads in row d
        if (qq < base + cnt) break;
        base += cnt; d++;
    }
    int j = qq - base;
    int e0 = (d & ~3) + 4 * j;
    g_qd8[qq] = d;
    g_qe0[qq] = e0;
#pragma unroll
    for (int s = 0; s < 4; s++) {
        int e = e0 + s;
        g_msl[qq * 4 + s] = (e < d) ? 0.f : ((e == d) ? 1.f : 2.f);
    }
}

// ---------------- K1: gating cumsum + derived weights ------------------------
__global__ void k_gate(const float* __restrict__ logg) {
    int ch = blockIdx.x;           // c*Hh + h
    int c = ch / Hh, h = ch % Hh;
    int l = threadIdx.x;
    __shared__ float sbuf[Ll];
    int t = c * Ll + l;
    sbuf[l] = logg[t * Hh + h];
    __syncthreads();
    for (int off = 1; off < Ll; off <<= 1) {
        float v   = sbuf[l];
        float add = (l >= off) ? sbuf[l - off] : 0.f;
        __syncthreads();
        sbuf[l] = v + add;
        __syncthreads();
    }
    float g    = sbuf[l];
    float gend = sbuf[Ll - 1];
    int idx = ch * Ll + l;
    g_g [idx] = g;
    g_w [idx] = expf(gend - g);
    g_qd[idx] = expf(g);
    if (l == 0) g_gtot[ch] = expf(gend);
}

// ---------------- K2: intra-chunk causal attention ---------------------------
__global__ void __launch_bounds__(128)
k_intra(const float* __restrict__ q, const float* __restrict__ k,
        const float* __restrict__ v) {
    int tl = 7 - blockIdx.x;
    int h = blockIdx.y, c = blockIdx.z;
    int lrow  = tl * 128 + threadIdx.x;
    int tglob = c * Ll + lrow;

    float qreg[Dd];
#pragma unroll
    for (int d = 0; d < Dd; d++)
        qreg[d] = q[(tglob * Hh + h) * Dd + d] * SCALEF;
    float gl = g_g[(c * Hh + h) * Ll + lrow];

    float acc[Dd];
#pragma unroll
    for (int d = 0; d < Dd; d++) acc[d] = 0.f;
    float rowsum = 0.f;

    __shared__ __align__(16) float Ks[64][68];
    __shared__ __align__(16) float Vs[64][68];
    __shared__ float Gs[64];

    int ntile = (tl + 1) * 2;
    for (int st = 0; st < ntile; st++) {
        int sbase = st * 64;
        __syncthreads();
        for (int idx = threadIdx.x; idx < 64 * Dd; idx += 128) {
            int r = idx >> 6, col = idx & 63;
            int ts = c * Ll + sbase + r;
            Ks[r][col] = k[(ts * Hh + h) * Dd + col];
            Vs[r][col] = v[(ts * Hh + h) * Dd + col];
        }
        if (threadIdx.x < 64)
            Gs[threadIdx.x] = g_g[(c * Hh + h) * Ll + sbase + threadIdx.x];
        __syncthreads();

        int smax = lrow - sbase + 1;
        if (smax > 64) smax = 64;
        for (int s = 0; s < smax; s++) {
            const float4* Kr = reinterpret_cast<const float4*>(&Ks[s][0]);
            float s0 = 0.f, s1 = 0.f, s2 = 0.f, s3 = 0.f;
#pragma unroll
            for (int d4 = 0; d4 < 16; d4++) {
                float4 kk = Kr[d4];
                s0 += qreg[4 * d4 + 0] * kk.x;
                s1 += qreg[4 * d4 + 1] * kk.y;
                s2 += qreg[4 * d4 + 2] * kk.z;
                s3 += qreg[4 * d4 + 3] * kk.w;
            }
            float sc = (s0 + s1) + (s2 + s3);
            float a  = __expf(gl - Gs[s]) * sc * sc;
            rowsum += a;
            const float4* Vr = reinterpret_cast<const float4*>(&Vs[s][0]);
#pragma unroll
            for (int d4 = 0; d4 < 16; d4++) {
                float4 vv = Vr[d4];
                acc[4 * d4 + 0] += a * vv.x;
                acc[4 * d4 + 1] += a * vv.y;
                acc[4 * d4 + 2] += a * vv.z;
                acc[4 * d4 + 3] += a * vv.w;
            }
        }
    }
    int ohid = tglob * Hh + h;
#pragma unroll
    for (int d = 0; d < Dd; d++) g_intra[ohid * Dd + d] = acc[d];
    g_row[ohid] = rowsum;
}

// ---------------- K3: per-chunk state build, F in registers ------------------
// Block: 32 quads (128 slots) x 65 v. Thread = (local quad) x (16-v group).
__global__ void __launch_bounds__(128)
k_state(const float* __restrict__ k, const float* __restrict__ v) {
    int h = blockIdx.y, c = blockIdx.z;
    int ch = c * Hh + h;
    int t = threadIdx.x;
    int lq = t >> 2;                   // local quad 0..31
    int vg = t & 3;                    // v group
    int v0 = vg * 16;
    int quad = blockIdx.x * 32 + lq;

    int d  = g_qd8[quad];
    int e0 = g_qe0[quad];
    float m0 = g_msl[quad * 4 + 0];
    float m1 = g_msl[quad * 4 + 1];
    float m2 = g_msl[quad * 4 + 2];
    float m3 = g_msl[quad * 4 + 3];

    __shared__ __align__(16) float Ks[32][68];
    __shared__ __align__(16) float Vs[32][68];   // V scaled by w; col 64 = w

    float acc[64];
#pragma unroll
    for (int x = 0; x < 64; x++) acc[x] = 0.f;
    float accZ[4] = {0.f, 0.f, 0.f, 0.f};

    const float* wb = g_w + ch * Ll;

    for (int lb = 0; lb < Ll; lb += 32) {
        __syncthreads();
        for (int idx = t; idx < 32 * Dd; idx += 128) {
            int r = idx >> 6, col = idx & 63;
            int ts = c * Ll + lb + r;
            Ks[r][col] = k[(ts * Hh + h) * Dd + col];
            Vs[r][col] = v[(ts * Hh + h) * Dd + col] * wb[lb + r];
        }
        if (t < 32) Vs[t][64] = wb[lb + t];
        __syncthreads();

#pragma unroll 4
        for (int l = 0; l < 32; l++) {
            float  kd = Ks[l][d];
            float4 ke = *reinterpret_cast<const float4*>(&Ks[l][e0]);
            float f0 = m0 * kd * ke.x;
            float f1 = m1 * kd * ke.y;
            float f2 = m2 * kd * ke.z;
            float f3 = m3 * kd * ke.w;
            const float4* Vr = reinterpret_cast<const float4*>(&Vs[l][v0]);
            float4 w0 = Vr[0], w1 = Vr[1], w2 = Vr[2], w3 = Vr[3];
            float fv[4] = {f0, f1, f2, f3};
#pragma unroll
            for (int j = 0; j < 4; j++) {
                float f = fv[j];
                acc[j*16+ 0] += f*w0.x; acc[j*16+ 1] += f*w0.y;
                acc[j*16+ 2] += f*w0.z; acc[j*16+ 3] += f*w0.w;
                acc[j*16+ 4] += f*w1.x; acc[j*16+ 5] += f*w1.y;
                acc[j*16+ 6] += f*w1.z; acc[j*16+ 7] += f*w1.w;
                acc[j*16+ 8] += f*w2.x; acc[j*16+ 9] += f*w2.y;
                acc[j*16+10] += f*w2.z; acc[j*16+11] += f*w2.w;
                acc[j*16+12] += f*w3.x; acc[j*16+13] += f*w3.y;
                acc[j*16+14] += f*w3.z; acc[j*16+15] += f*w3.w;
            }
            if (vg == 3) {
                float wl = Vs[l][64];
                accZ[0] += f0 * wl; accZ[1] += f1 * wl;
                accZ[2] += f2 * wl; accZ[3] += f3 * wl;
            }
        }
    }

    size_t pbase = ((size_t)ch * NSLOT + (size_t)quad * 4) * NVP;
#pragma unroll
    for (int j = 0; j < 4; j++) {
        float* dst = &g_P[pbase + (size_t)j * NVP + v0];
#pragma unroll
        for (int x = 0; x < 4; x++)
            *reinterpret_cast<float4*>(&dst[x * 4]) =
                make_float4(acc[j*16+x*4+0], acc[j*16+x*4+1],
                            acc[j*16+x*4+2], acc[j*16+x*4+3]);
        if (vg == 3)
            g_P[pbase + (size_t)j * NVP + 64] = accZ[j];
    }
}

// ---------------- K4: pure prefix scan over chunks ---------------------------
__global__ void k_scan() {
    int idx = blockIdx.x * blockDim.x + threadIdx.x;
    const int per_h = NSLOT * NVP;
    const int tot = Hh * per_h;
    if (idx >= tot) return;
    int h = idx / per_h;
    int rem = idx % per_h;
    float s = 0.f;
    for (int c = 0; c < Cc; c++) {
        size_t off = (size_t)(c * Hh + h) * per_h + rem;
        g_S[off] = s;                              // state BEFORE chunk c
        s = g_gtot[c * Hh + h] * s + g_P[off];
    }
}

// ---------------- K5: inter-chunk GEMM + combine (F on the fly) --------------
// Block: 128 rows x 65 v. Thread = (row group of 4) x (16-v group).
__global__ void __launch_bounds__(128)
k_inter(const float* __restrict__ q, float* __restrict__ out) {
    __shared__ float Qs[128 * 65];                 // stride 65 -> conflict-free
    __shared__ __align__(16) float Ss[32 * 68];
    __shared__ int Pd2[32], Pe2[32];
    __shared__ float SInv[128];

    int tl = blockIdx.x, h = blockIdx.y, c = blockIdx.z;
    int ch = c * Hh + h;
    int t = threadIdx.x;
    int rg = t >> 2, vg = t & 3, v0 = vg * 16;

    for (int idx = t; idx < 128 * Dd; idx += 128) {
        int r = idx >> 6, col = idx & 63;
        int tg = c * Ll + tl * 128 + r;
        Qs[r * 65 + col] = q[(tg * Hh + h) * Dd + col] * SCALEF;
    }
    __syncthreads();

    float acc[64];
#pragma unroll
    for (int x = 0; x < 64; x++) acc[x] = 0.f;
    float accZ[4] = {0.f, 0.f, 0.f, 0.f};

    if (c > 0) {
        const float* Sbase = &g_S[(size_t)ch * NSLOT * NVP];
        for (int ib = 0; ib < NSLOT; ib += 32) {
            __syncthreads();
            const float4* src = reinterpret_cast<const float4*>(Sbase + (size_t)ib * NVP);
            float4* dstS = reinterpret_cast<float4*>(Ss);
            for (int idx = t; idx < 32 * NVP / 4; idx += 128) dstS[idx] = src[idx];
            if (t < 32) {
                int s = ib + t;
                Pd2[t] = g_qd8[s >> 2];
                Pe2[t] = g_qe0[s >> 2] + (s & 3);
            }
            __syncthreads();
#pragma unroll 4
            for (int ii = 0; ii < 32; ii++) {
                int dd = Pd2[ii], ee = Pe2[ii];
                float f0 = Qs[(rg*4+0)*65 + dd] * Qs[(rg*4+0)*65 + ee];
                float f1 = Qs[(rg*4+1)*65 + dd] * Qs[(rg*4+1)*65 + ee];
                float f2 = Qs[(rg*4+2)*65 + dd] * Qs[(rg*4+2)*65 + ee];
                float f3 = Qs[(rg*4+3)*65 + dd] * Qs[(rg*4+3)*65 + ee];
                const float4* Sr = reinterpret_cast<const float4*>(&Ss[ii * 68 + v0]);
                float4 s0 = Sr[0], s1 = Sr[1], s2 = Sr[2], s3 = Sr[3];
                float fv[4] = {f0, f1, f2, f3};
#pragma unroll
                for (int j = 0; j < 4; j++) {
                    float f = fv[j];
                    acc[j*16+ 0] += f*s0.x; acc[j*16+ 1] += f*s0.y;
                    acc[j*16+ 2] += f*s0.z; acc[j*16+ 3] += f*s0.w;
                    acc[j*16+ 4] += f*s1.x; acc[j*16+ 5] += f*s1.y;
                    acc[j*16+ 6] += f*s1.z; acc[j*16+ 7] += f*s1.w;
                    acc[j*16+ 8] += f*s2.x; acc[j*16+ 9] += f*s2.y;
                    acc[j*16+10] += f*s2.z; acc[j*16+11] += f*s2.w;
                    acc[j*16+12] += f*s3.x; acc[j*16+13] += f*s3.y;
                    acc[j*16+14] += f*s3.z; acc[j*16+15] += f*s3.w;
                }
                if (vg == 0) {
                    float sz = Ss[ii * 68 + 64];
                    accZ[0] += f0 * sz; accZ[1] += f1 * sz;
                    accZ[2] += f2 * sz; accZ[3] += f3 * sz;
                }
            }
        }
    }

    __syncthreads();
    if (vg == 0) {
#pragma unroll
        for (int j = 0; j < 4; j++) {
            int r = rg * 4 + j;
            int tg = c * Ll + tl * 128 + r;
            float qd = g_qd[ch * Ll + tl * 128 + r];
            float den = g_row[tg * Hh + h] + qd * accZ[j];
            SInv[r] = 1.f / fmaxf(den, EPSF);
        }
    }
    __syncthreads();
#pragma unroll
    for (int j = 0; j < 4; j++) {
        int r = rg * 4 + j;
        int tg = c * Ll + tl * 128 + r;
        int ohid = tg * Hh + h;
        float qd = g_qd[ch * Ll + tl * 128 + r];
        float inv = SInv[r];
        const float4* Ir = reinterpret_cast<const float4*>(&g_intra[(size_t)ohid * Dd + v0]);
        float4* Or = reinterpret_cast<float4*>(&out[(size_t)ohid * Dd + v0]);
#pragma unroll
        for (int x = 0; x < 4; x++) {
            float4 iv = Ir[x];
            Or[x] = make_float4((iv.x + qd * acc[j*16+x*4+0]) * inv,
                                (iv.y + qd * acc[j*16+x*4+1]) * inv,
                                (iv.z + qd * acc[j*16+x*4+2]) * inv,
                                (iv.w + qd * acc[j*16+x*4+3]) * inv);
        }
    }
}

// ---------------- host launch -------------------------------------------------
extern "C" void kernel_launch(void* const* d_in, const int* in_sizes, int n_in,
                              void* d_out, int out_size) {
    const float* q  = (const float*)d_in[0];
    const float* k  = (const float*)d_in[1];
    const float* v  = (const float*)d_in[2];
    const float* lg = (const float*)d_in[3];
    float* out = (float*)d_out;

    k_pairs<<<(NQUAD + 127) / 128, 128>>>();
    k_gate <<<Cc * Hh, Ll>>>(lg);
    k_intra<<<dim3(8, Hh, Cc), 128>>>(q, k, v);
    k_state<<<dim3(NQUAD / 32, Hh, Cc), 128>>>(k, v);
    k_scan <<<(Hh * NSLOT * NVP + 255) / 256, 256>>>();
    k_inter<<<dim3(8, Hh, Cc), 128>>>(q, out);
}

// round 14
// speedup vs baseline: 1.3384x; 1.2622x over previous
#include <cuda_runtime.h>
#include <math.h>
#include <stdint.h>

// Problem constants (B=1)
#define Cc    4      // chunks
#define Hh    8      // heads
#define Ll    1024   // chunk length
#define Dd    64     // head dim
#define Tt    (Cc*Ll)
#define NQUAD 544    // quads: (d, e0) with e0 = (d&~3)+4j
#define NSLOT 2176   // NQUAD*4 slots (invalid e<d slots have multiplier 0)
#define NVP   68     // padded row: 64 v + Z at col 64 + 3 pad
#define SCALEF 0.125f
#define EPSF   1e-6f

// ---------------- scratch (device globals; no allocation allowed) -----------
__device__ float g_g   [Cc*Hh*Ll];
__device__ float g_w   [Cc*Hh*Ll];
__device__ float g_qd  [Cc*Hh*Ll];
__device__ float g_gtot[Cc*Hh];
__device__ float g_P   [Cc*Hh*NSLOT*NVP];
__device__ float g_S   [Cc*Hh*NSLOT*NVP];
__device__ float g_intra[Tt*Hh*Dd];
__device__ float g_row  [Tt*Hh];
__device__ int   g_qd8 [NQUAD];     // quad -> d
__device__ int   g_qe0 [NQUAD];     // quad -> e0
__device__ float g_msl [NSLOT];     // slot multiplier: 0 (e<d), 1 (e==d), 2 (e>d)

// ---------------- mma.sync tf32 helper (baseline PTX, works on sm_103) -------
__device__ __forceinline__ void mma_tf32(float* c, const uint32_t* a,
                                         uint32_t b0, uint32_t b1) {
    asm volatile(
        "mma.sync.aligned.m16n8k8.row.col.f32.tf32.tf32.f32 "
        "{%0,%1,%2,%3}, {%4,%5,%6,%7}, {%8,%9}, {%0,%1,%2,%3};"
        : "+f"(c[0]), "+f"(c[1]), "+f"(c[2]), "+f"(c[3])
        : "r"(a[0]), "r"(a[1]), "r"(a[2]), "r"(a[3]), "r"(b0), "r"(b1));
}

// ---------------- K0: quad tables ---------------------------------------------
__global__ void k_pairs() {
    int qq = blockIdx.x * blockDim.x + threadIdx.x;
    if (qq >= NQUAD) return;
    int d = 0, base = 0;
    for (;;) {
        int cnt = 16 - (d >> 2);
        if (qq < base + cnt) break;
        base += cnt; d++;
    }
    int j = qq - base;
    int e0 = (d & ~3) + 4 * j;
    g_qd8[qq] = d;
    g_qe0[qq] = e0;
#pragma unroll
    for (int s = 0; s < 4; s++) {
        int e = e0 + s;
        g_msl[qq * 4 + s] = (e < d) ? 0.f : ((e == d) ? 1.f : 2.f);
    }
}

// ---------------- K1: gating cumsum + derived weights ------------------------
__global__ void k_gate(const float* __restrict__ logg) {
    int ch = blockIdx.x;
    int c = ch / Hh, h = ch % Hh;
    int l = threadIdx.x;
    __shared__ float sbuf[Ll];
    int t = c * Ll + l;
    sbuf[l] = logg[t * Hh + h];
    __syncthreads();
    for (int off = 1; off < Ll; off <<= 1) {
        float v   = sbuf[l];
        float add = (l >= off) ? sbuf[l - off] : 0.f;
        __syncthreads();
        sbuf[l] = v + add;
        __syncthreads();
    }
    float g    = sbuf[l];
    float gend = sbuf[Ll - 1];
    int idx = ch * Ll + l;
    g_g [idx] = g;
    g_w [idx] = expf(gend - g);
    g_qd[idx] = expf(g);
    if (l == 0) g_gtot[ch] = expf(gend);
}

// ---------------- K2: intra-chunk causal attention (scalar, unchanged) -------
__global__ void __launch_bounds__(128)
k_intra(const float* __restrict__ q, const float* __restrict__ k,
        const float* __restrict__ v) {
    int tl = 7 - blockIdx.x;
    int h = blockIdx.y, c = blockIdx.z;
    int lrow  = tl * 128 + threadIdx.x;
    int tglob = c * Ll + lrow;

    float qreg[Dd];
#pragma unroll
    for (int d = 0; d < Dd; d++)
        qreg[d] = q[(tglob * Hh + h) * Dd + d] * SCALEF;
    float gl = g_g[(c * Hh + h) * Ll + lrow];

    float acc[Dd];
#pragma unroll
    for (int d = 0; d < Dd; d++) acc[d] = 0.f;
    float rowsum = 0.f;

    __shared__ __align__(16) float Ks[64][68];
    __shared__ __align__(16) float Vs[64][68];
    __shared__ float Gs[64];

    int ntile = (tl + 1) * 2;
    for (int st = 0; st < ntile; st++) {
        int sbase = st * 64;
        __syncthreads();
        for (int idx = threadIdx.x; idx < 64 * Dd; idx += 128) {
            int r = idx >> 6, col = idx & 63;
            int ts = c * Ll + sbase + r;
            Ks[r][col] = k[(ts * Hh + h) * Dd + col];
            Vs[r][col] = v[(ts * Hh + h) * Dd + col];
        }
        if (threadIdx.x < 64)
            Gs[threadIdx.x] = g_g[(c * Hh + h) * Ll + sbase + threadIdx.x];
        __syncthreads();

        int smax = lrow - sbase + 1;
        if (smax > 64) smax = 64;
        for (int s = 0; s < smax; s++) {
            const float4* Kr = reinterpret_cast<const float4*>(&Ks[s][0]);
            float s0 = 0.f, s1 = 0.f, s2 = 0.f, s3 = 0.f;
#pragma unroll
            for (int d4 = 0; d4 < 16; d4++) {
                float4 kk = Kr[d4];
                s0 += qreg[4 * d4 + 0] * kk.x;
                s1 += qreg[4 * d4 + 1] * kk.y;
                s2 += qreg[4 * d4 + 2] * kk.z;
                s3 += qreg[4 * d4 + 3] * kk.w;
            }
            float sc = (s0 + s1) + (s2 + s3);
            float a  = __expf(gl - Gs[s]) * sc * sc;
            rowsum += a;
            const float4* Vr = reinterpret_cast<const float4*>(&Vs[s][0]);
#pragma unroll
            for (int d4 = 0; d4 < 16; d4++) {
                float4 vv = Vr[d4];
                acc[4 * d4 + 0] += a * vv.x;
                acc[4 * d4 + 1] += a * vv.y;
                acc[4 * d4 + 2] += a * vv.z;
                acc[4 * d4 + 3] += a * vv.w;
            }
        }
    }
    int ohid = tglob * Hh + h;
#pragma unroll
    for (int d = 0; d < Dd; d++) g_intra[ohid * Dd + d] = acc[d];
    g_row[ohid] = rowsum;
}

// ---------------- K3: state build via mma.sync tf32x3 ------------------------
// Per CTA: M=128 slots, N=72 (64 V·w + w col for Z + pad), K=1024.
// 4 warps; warp w owns rows w*32..w*32+31 (2 m-frags), all 9 n-frags.
__global__ void __launch_bounds__(128)
k_state_mma(const float* __restrict__ k, const float* __restrict__ v) {
    __shared__ float  Kraw[32 * 65];
    __shared__ __align__(8) float2 Bt[32 * 73];   // (hi, lo) of (V·w | w | 0)

    int mt = blockIdx.x, h = blockIdx.y, c = blockIdx.z;
    int ch = c * Hh + h;
    int t = threadIdx.x;
    int w = t >> 5, lane = t & 31, gid = lane >> 2, tig = lane & 3;

    // per-thread row metadata (4 rows: gid, gid+8, gid+16, gid+24 within warp tile)
    int dR[4], eR[4];
    float mR[4];
#pragma unroll
    for (int j = 0; j < 4; j++) {
        int slot = mt * 128 + w * 32 + gid + 8 * j;
        dR[j] = g_qd8[slot >> 2];
        eR[j] = g_qe0[slot >> 2] + (slot & 3);
        mR[j] = g_msl[slot];
    }

    float acc[72];
#pragma unroll
    for (int x = 0; x < 72; x++) acc[x] = 0.f;

    const float* wb = g_w + ch * Ll;

    for (int tile = 0; tile < 32; tile++) {
        int lb = tile * 32;
        __syncthreads();
        // stage K tile
        for (int idx = t; idx < 32 * 64; idx += 128) {
            int r = idx >> 6, col = idx & 63;
            Kraw[r * 65 + col] = k[((size_t)((c * Ll + lb + r) * Hh + h)) * Dd + col];
        }
        // stage B = (V·w | w | 0) split hi/lo interleaved
        for (int idx = t; idx < 32 * 72; idx += 128) {
            int r = idx / 72, col = idx - r * 72;
            float wr = wb[lb + r];
            float val;
            if (col < 64)      val = v[((size_t)((c * Ll + lb + r) * Hh + h)) * Dd + col] * wr;
            else if (col == 64) val = wr;
            else                val = 0.f;
            uint32_t hb = __float_as_uint(val) & 0xFFFFE000u;
            float hf = __uint_as_float(hb);
            Bt[r * 73 + col] = make_float2(hf, val - hf);
        }
        __syncthreads();

#pragma unroll
        for (int ks = 0; ks < 4; ks++) {
            int l0 = ks * 8 + tig, l1 = l0 + 4;
            uint32_t ahi[2][4], alo[2][4];
#pragma unroll
            for (int j = 0; j < 4; j++) {
                float f0 = mR[j] * Kraw[l0 * 65 + dR[j]] * Kraw[l0 * 65 + eR[j]];
                float f1 = mR[j] * Kraw[l1 * 65 + dR[j]] * Kraw[l1 * 65 + eR[j]];
                uint32_t h0 = __float_as_uint(f0) & 0xFFFFE000u;
                uint32_t h1 = __float_as_uint(f1) & 0xFFFFE000u;
                int mf = j >> 1, rr = j & 1;
                ahi[mf][rr]     = h0;
                ahi[mf][rr + 2] = h1;
                alo[mf][rr]     = __float_as_uint(f0 - __uint_as_float(h0));
                alo[mf][rr + 2] = __float_as_uint(f1 - __uint_as_float(h1));
            }
#pragma unroll
            for (int nf = 0; nf < 9; nf++) {
                float2 B0 = Bt[l0 * 73 + nf * 8 + gid];
                float2 B1 = Bt[l1 * 73 + nf * 8 + gid];
                uint32_t bh0 = __float_as_uint(B0.x), bl0 = __float_as_uint(B0.y);
                uint32_t bh1 = __float_as_uint(B1.x), bl1 = __float_as_uint(B1.y);
#pragma unroll
                for (int mf = 0; mf < 2; mf++) {
                    float* cc = acc + (mf * 9 + nf) * 4;
                    mma_tf32(cc, ahi[mf], bh0, bh1);
                    mma_tf32(cc, ahi[mf], bl0, bl1);
                    mma_tf32(cc, alo[mf], bh0, bh1);
                }
            }
        }
    }

    // epilogue: D[row][col] -> g_P
#pragma unroll
    for (int j = 0; j < 4; j++) {
        int slot = mt * 128 + w * 32 + gid + 8 * j;
        size_t base = ((size_t)ch * NSLOT + slot) * NVP;
        int mf = j >> 1, rr = j & 1;
#pragma unroll
        for (int nf = 0; nf < 9; nf++) {
            int col = nf * 8 + tig * 2;
            float v0 = acc[(mf * 9 + nf) * 4 + rr * 2];
            float v1 = acc[(mf * 9 + nf) * 4 + rr * 2 + 1];
            if (col < 64)
                *reinterpret_cast<float2*>(&g_P[base + col]) = make_float2(v0, v1);
            else if (col == 64)
                g_P[base + 64] = v0;
        }
    }
}

// ---------------- K4: pure prefix scan over chunks ---------------------------
__global__ void k_scan() {
    int idx = blockIdx.x * blockDim.x + threadIdx.x;
    const int per_h = NSLOT * NVP;
    const int tot = Hh * per_h;
    if (idx >= tot) return;
    int h = idx / per_h;
    int rem = idx % per_h;
    float s = 0.f;
    for (int c = 0; c < Cc; c++) {
        size_t off = (size_t)(c * Hh + h) * per_h + rem;
        g_S[off] = s;
        s = g_gtot[c * Hh + h] * s + g_P[off];
    }
}

// ---------------- K5: inter-chunk GEMM via mma.sync tf32x3 + combine ---------
// Per CTA: M=128 q-rows, N=72 (64 out + Z col), K=NSLOT=2176.
#define ISM_QS   0
#define ISM_BS   (128 * 65 * 4)                      // 33280
#define ISM_DS   (ISM_BS + 32 * 73 * 8)              // 51968
#define ISM_ES   (ISM_DS + 32 * 4)
#define ISM_SIZE (ISM_ES + 32 * 4)                   // 52224

__global__ void __launch_bounds__(128)
k_inter_mma(const float* __restrict__ q, float* __restrict__ out) {
    extern __shared__ char ism[];
    float*  Qs  = reinterpret_cast<float*>(ism + ISM_QS);
    float2* Bs  = reinterpret_cast<float2*>(ism + ISM_BS);
    int*    sDs = reinterpret_cast<int*>(ism + ISM_DS);
    int*    sEs = reinterpret_cast<int*>(ism + ISM_ES);

    int tl = blockIdx.x, h = blockIdx.y, c = blockIdx.z;
    int ch = c * Hh + h;
    int t = threadIdx.x;
    int w = t >> 5, lane = t & 31, gid = lane >> 2, tig = lane & 3;

    // stage Q tile (128 rows x 64, stride 65)
    for (int idx = t; idx < 128 * 64; idx += 128) {
        int r = idx >> 6, col = idx & 63;
        int tg = c * Ll + tl * 128 + r;
        Qs[r * 65 + col] = q[((size_t)(tg * Hh + h)) * Dd + col] * SCALEF;
    }
    __syncthreads();

    float acc[72];
#pragma unroll
    for (int x = 0; x < 72; x++) acc[x] = 0.f;

    int Rrow[4];
#pragma unroll
    for (int j = 0; j < 4; j++) Rrow[j] = w * 32 + gid + 8 * j;

    if (c > 0) {
        const float* Sbase = &g_S[(size_t)ch * NSLOT * NVP];
        for (int kb = 0; kb < NSLOT; kb += 32) {
            __syncthreads();
            for (int idx = t; idx < 32 * 72; idx += 128) {
                int r = idx / 72, col = idx - r * 72;
                float val = (col <= 64) ? Sbase[(size_t)(kb + r) * NVP + col] : 0.f;
                uint32_t hb = __float_as_uint(val) & 0xFFFFE000u;
                float hf = __uint_as_float(hb);
                Bs[r * 73 + col] = make_float2(hf, val - hf);
            }
            if (t < 32) {
                int s = kb + t;
                sDs[t] = g_qd8[s >> 2];
                sEs[t] = g_qe0[s >> 2] + (s & 3);
            }
            __syncthreads();

#pragma unroll
            for (int ks = 0; ks < 4; ks++) {
                int ls0 = ks * 8 + tig, ls1 = ls0 + 4;
                int d0 = sDs[ls0], e0 = sEs[ls0];
                int d1 = sDs[ls1], e1 = sEs[ls1];
                uint32_t ahi[2][4], alo[2][4];
#pragma unroll
                for (int j = 0; j < 4; j++) {
                    const float* qr = &Qs[Rrow[j] * 65];
                    float f0 = qr[d0] * qr[e0];
                    float f1 = qr[d1] * qr[e1];
                    uint32_t h0 = __float_as_uint(f0) & 0xFFFFE000u;
                    uint32_t h1 = __float_as_uint(f1) & 0xFFFFE000u;
                    int mf = j >> 1, rr = j & 1;
                    ahi[mf][rr]     = h0;
                    ahi[mf][rr + 2] = h1;
                    alo[mf][rr]     = __float_as_uint(f0 - __uint_as_float(h0));
                    alo[mf][rr + 2] = __float_as_uint(f1 - __uint_as_float(h1));
                }
#pragma unroll
                for (int nf = 0; nf < 9; nf++) {
                    float2 B0 = Bs[ls0 * 73 + nf * 8 + gid];
                    float2 B1 = Bs[ls1 * 73 + nf * 8 + gid];
                    uint32_t bh0 = __float_as_uint(B0.x), bl0 = __float_as_uint(B0.y);
                    uint32_t bh1 = __float_as_uint(B1.x), bl1 = __float_as_uint(B1.y);
#pragma unroll
                    for (int mf = 0; mf < 2; mf++) {
                        float* cc = acc + (mf * 9 + nf) * 4;
                        mma_tf32(cc, ahi[mf], bh0, bh1);
                        mma_tf32(cc, ahi[mf], bl0, bl1);
                        mma_tf32(cc, alo[mf], bh0, bh1);
                    }
                }
            }
        }
    }

    // epilogue: den + combine with intra
    float invj[4], qdj[4];
#pragma unroll
    for (int j = 0; j < 4; j++) {
        int rl = tl * 128 + Rrow[j];
        qdj[j] = g_qd[ch * Ll + rl];
        float Z = acc[((j >> 1) * 9 + 8) * 4 + (j & 1) * 2];   // col 64 (valid on tig==0)
        float den = g_row[(c * Ll + rl) * Hh + h] + qdj[j] * Z;
        float inv = 1.f / fmaxf(den, EPSF);
        invj[j] = __shfl_sync(0xffffffffu, inv, lane & ~3, 32);
    }
#pragma unroll
    for (int j = 0; j < 4; j++) {
        int rl = tl * 128 + Rrow[j];
        int ohid = (c * Ll + rl) * Hh + h;
        int mf = j >> 1, rr = j & 1;
#pragma unroll
        for (int nf = 0; nf < 8; nf++) {
            int col = nf * 8 + tig * 2;
            float a0 = acc[(mf * 9 + nf) * 4 + rr * 2];
            float a1 = acc[(mf * 9 + nf) * 4 + rr * 2 + 1];
            float2 iv = *reinterpret_cast<const float2*>(&g_intra[(size_t)ohid * Dd + col]);
            float2 o;
            o.x = (iv.x + qdj[j] * a0) * invj[j];
            o.y = (iv.y + qdj[j] * a1) * invj[j];
            *reinterpret_cast<float2*>(&out[(size_t)ohid * Dd + col]) = o;
        }
    }
}

// ---------------- host launch -------------------------------------------------
extern "C" void kernel_launch(void* const* d_in, const int* in_sizes, int n_in,
                              void* d_out, int out_size) {
    const float* q  = (const float*)d_in[0];
    const float* k  = (const float*)d_in[1];
    const float* v  = (const float*)d_in[2];
    const float* lg = (const float*)d_in[3];
    float* out = (float*)d_out;

    cudaFuncSetAttribute(k_inter_mma,
                         cudaFuncAttributeMaxDynamicSharedMemorySize, ISM_SIZE);

    k_pairs<<<(NQUAD + 127) / 128, 128>>>();
    k_gate <<<Cc * Hh, Ll>>>(lg);
    k_intra<<<dim3(8, Hh, Cc), 128>>>(q, k, v);
    k_state_mma<<<dim3(NSLOT / 128, Hh, Cc), 128>>>(k, v);
    k_scan <<<(Hh * NSLOT * NVP + 255) / 256, 256>>>();
    k_inter_mma<<<dim3(8, Hh, Cc), 128, ISM_SIZE>>>(q, out);
}